// round 3
// baseline (speedup 1.0000x reference)
#include <cuda_runtime.h>
#include <math.h>

// ------------------------- problem sizes -------------------------
#define BATCH 8
#define NTOK  4096
#define CDIM  512
#define HDIM  64
#define HH    4       // heads per branch
#define H0    64
#define W0    64
// branch 1: conv 5x5 stride 4 pad 1 -> 16x16
#define N1 256
#define H1 16
#define W1 16
#define KHW1 25
#define K1 (KHW1*CDIM)   // 12800
// branch 2: conv 3x3 stride 2 pad 1 -> 32x32
#define N2 1024
#define H2 32
#define W2 32
#define KHW2 9
#define K2 (KHW2*CDIM)   // 4608

// ------------------------- scratch (device globals; no allocation) -------------------------
__device__ float g_q   [BATCH*NTOK*CDIM];
__device__ float g_wt1 [CDIM*K1];
__device__ float g_wt2 [CDIM*K2];
__device__ float g_x1  [BATCH*N1*CDIM];
__device__ float g_x2  [BATCH*N2*CDIM];
__device__ float g_kv1 [BATCH*N1*CDIM];
__device__ float g_kv2 [BATCH*N2*CDIM];
__device__ float g_v1  [BATCH*HH*N1*HDIM];
__device__ float g_v2  [BATCH*HH*N2*HDIM];
__device__ float g_att [BATCH*NTOK*CDIM];

// ------------------------- weight transpose: OIHW -> [co][s][ci] -------------------------
__global__ void wtrans_kernel(const float* __restrict__ w, float* __restrict__ wt, int KHW) {
    int idx = blockIdx.x * 256 + threadIdx.x;
    int total = CDIM * KHW * CDIM;
    if (idx >= total) return;
    int ci = idx % CDIM;
    int s  = (idx / CDIM) % KHW;
    int co = idx / (CDIM * KHW);
    wt[idx] = w[(co * CDIM + ci) * KHW + s];
}

// ------------------------- implicit-GEMM conv: C[m, co] = sum_k im2col(x)[m,k] * Wt[co,k] -------------------------
// Wt: [CDIM rows][K = KHW*512], k = s*512+ci. 128x128 tile, KT=16, 256 threads, 8x8/thread.
template<int OWS, int KW, int STRIDE>
__global__ void __launch_bounds__(256) convgemm_kernel(
    const float* __restrict__ x, const float* __restrict__ Bw,
    const float* __restrict__ bias, float* __restrict__ C, int K) {
    __shared__ float As[16][128];
    __shared__ float Bs[16][128];
    const int tid = threadIdx.x;
    const int tx = tid & 15, ty = tid >> 4;
    const int N = CDIM;

    float acc[8][8];
#pragma unroll
    for (int i = 0; i < 8; i++)
#pragma unroll
        for (int j = 0; j < 8; j++) acc[i][j] = 0.f;

    for (int k0 = 0; k0 < K; k0 += 16) {
        // implicit im2col A load
#pragma unroll
        for (int it = 0; it < 2; it++) {
            int f = tid + it * 256;
            int row = f >> 2;
            int kk4 = (f & 3) * 4;
            int k = k0 + kk4;
            int s = k >> 9;
            int ci = k & 511;
            int kh = s / KW, kw = s - kh * KW;
            int m = blockIdx.y * 128 + row;
            int b = m >> (2 * OWS);
            int pos = m & ((1 << (2 * OWS)) - 1);
            int oh = pos >> OWS;
            int ow = pos & ((1 << OWS) - 1);
            int ih = oh * STRIDE - 1 + kh;
            int iw = ow * STRIDE - 1 + kw;
            float4 v = make_float4(0.f, 0.f, 0.f, 0.f);
            if (ih >= 0 && ih < H0 && iw >= 0 && iw < W0)
                v = *(const float4*)(x + ((size_t)b * NTOK + ih * W0 + iw) * CDIM + ci);
            As[kk4 + 0][row] = v.x; As[kk4 + 1][row] = v.y;
            As[kk4 + 2][row] = v.z; As[kk4 + 3][row] = v.w;
        }
        // B load (weights, [N rows][K]) transposed into Bs[k][n]
#pragma unroll
        for (int it = 0; it < 2; it++) {
            int f = tid + it * 256;
            int row = f >> 2;
            int kk4 = (f & 3) * 4;
            float4 v = *(const float4*)(Bw + (size_t)(blockIdx.x * 128 + row) * K + k0 + kk4);
            Bs[kk4 + 0][row] = v.x; Bs[kk4 + 1][row] = v.y;
            Bs[kk4 + 2][row] = v.z; Bs[kk4 + 3][row] = v.w;
        }
        __syncthreads();
#pragma unroll
        for (int kk = 0; kk < 16; kk++) {
            float4 a0 = *(const float4*)&As[kk][ty * 4];
            float4 a1 = *(const float4*)&As[kk][64 + ty * 4];
            float4 b0 = *(const float4*)&Bs[kk][tx * 4];
            float4 b1 = *(const float4*)&Bs[kk][64 + tx * 4];
            float ar[8] = {a0.x, a0.y, a0.z, a0.w, a1.x, a1.y, a1.z, a1.w};
            float br[8] = {b0.x, b0.y, b0.z, b0.w, b1.x, b1.y, b1.z, b1.w};
#pragma unroll
            for (int i = 0; i < 8; i++)
#pragma unroll
                for (int j = 0; j < 8; j++) acc[i][j] += ar[i] * br[j];
        }
        __syncthreads();
    }
#pragma unroll
    for (int ih = 0; ih < 2; ih++)
#pragma unroll
        for (int i = 0; i < 4; i++) {
            int row = blockIdx.y * 128 + ih * 64 + ty * 4 + i;
#pragma unroll
            for (int jh = 0; jh < 2; jh++) {
                int col = blockIdx.x * 128 + jh * 64 + tx * 4;
                float4 o;
                o.x = acc[ih * 4 + i][jh * 4 + 0] + bias[col];
                o.y = acc[ih * 4 + i][jh * 4 + 1] + bias[col + 1];
                o.z = acc[ih * 4 + i][jh * 4 + 2] + bias[col + 2];
                o.w = acc[ih * 4 + i][jh * 4 + 3] + bias[col + 3];
                *(float4*)(C + (size_t)row * N + col) = o;
            }
        }
}

// ------------------------- tiled SGEMM: C = A * B (+bias), B [K,N] row-major -------------------------
template<bool BIAS>
__global__ void __launch_bounds__(256) sgemm_kernel(
    const float* __restrict__ A, const float* __restrict__ B,
    const float* __restrict__ bias, float* __restrict__ C,
    int M, int N, int K) {
    __shared__ float As[16][128];
    __shared__ float Bs[16][128];
    const int tid = threadIdx.x;
    const int tx = tid & 15, ty = tid >> 4;
    const size_t aBase = (size_t)blockIdx.y * 128 * K;

    float acc[8][8];
#pragma unroll
    for (int i = 0; i < 8; i++)
#pragma unroll
        for (int j = 0; j < 8; j++) acc[i][j] = 0.f;

    for (int k0 = 0; k0 < K; k0 += 16) {
#pragma unroll
        for (int it = 0; it < 2; it++) {
            int f = tid + it * 256;
            int row = f >> 2;
            int kk4 = (f & 3) * 4;
            float4 v = *(const float4*)(A + aBase + (size_t)row * K + k0 + kk4);
            As[kk4 + 0][row] = v.x; As[kk4 + 1][row] = v.y;
            As[kk4 + 2][row] = v.z; As[kk4 + 3][row] = v.w;
        }
#pragma unroll
        for (int it = 0; it < 2; it++) {
            int f = tid + it * 256;
            int kk = f >> 5;
            int nn = (f & 31) * 4;
            float4 v = *(const float4*)(B + (size_t)(k0 + kk) * N + blockIdx.x * 128 + nn);
            *(float4*)&Bs[kk][nn] = v;
        }
        __syncthreads();
#pragma unroll
        for (int kk = 0; kk < 16; kk++) {
            float4 a0 = *(const float4*)&As[kk][ty * 4];
            float4 a1 = *(const float4*)&As[kk][64 + ty * 4];
            float4 b0 = *(const float4*)&Bs[kk][tx * 4];
            float4 b1 = *(const float4*)&Bs[kk][64 + tx * 4];
            float ar[8] = {a0.x, a0.y, a0.z, a0.w, a1.x, a1.y, a1.z, a1.w};
            float br[8] = {b0.x, b0.y, b0.z, b0.w, b1.x, b1.y, b1.z, b1.w};
#pragma unroll
            for (int i = 0; i < 8; i++)
#pragma unroll
                for (int j = 0; j < 8; j++) acc[i][j] += ar[i] * br[j];
        }
        __syncthreads();
    }
#pragma unroll
    for (int ih = 0; ih < 2; ih++)
#pragma unroll
        for (int i = 0; i < 4; i++) {
            int row = blockIdx.y * 128 + ih * 64 + ty * 4 + i;
#pragma unroll
            for (int jh = 0; jh < 2; jh++) {
                int col = blockIdx.x * 128 + jh * 64 + tx * 4;
                float4 o;
                o.x = acc[ih * 4 + i][jh * 4 + 0];
                o.y = acc[ih * 4 + i][jh * 4 + 1];
                o.z = acc[ih * 4 + i][jh * 4 + 2];
                o.w = acc[ih * 4 + i][jh * 4 + 3];
                if (BIAS) {
                    o.x += bias[col]; o.y += bias[col + 1];
                    o.z += bias[col + 2]; o.w += bias[col + 3];
                }
                *(float4*)(C + (size_t)row * N + col) = o;
            }
        }
}

// ------------------------- LayerNorm + exact GELU (in place, rows of 512) -------------------------
__global__ void ln_gelu_kernel(float* __restrict__ x, const float* __restrict__ gw,
                               const float* __restrict__ gb) {
    __shared__ float rs_[4], rs2_[4];
    int row = blockIdx.x;
    int t = threadIdx.x;   // 128
    float4* p = (float4*)(x + (size_t)row * CDIM);
    float4 v = p[t];
    float s  = v.x + v.y + v.z + v.w;
    float s2 = v.x * v.x + v.y * v.y + v.z * v.z + v.w * v.w;
#pragma unroll
    for (int o = 16; o; o >>= 1) {
        s  += __shfl_xor_sync(0xffffffffu, s, o);
        s2 += __shfl_xor_sync(0xffffffffu, s2, o);
    }
    int wid = t >> 5;
    if ((t & 31) == 0) { rs_[wid] = s; rs2_[wid] = s2; }
    __syncthreads();
    s  = rs_[0] + rs_[1] + rs_[2] + rs_[3];
    s2 = rs2_[0] + rs2_[1] + rs2_[2] + rs2_[3];
    float mean = s * (1.f / 512.f);
    float var  = s2 * (1.f / 512.f) - mean * mean;
    float rstd = rsqrtf(var + 1e-5f);
    int c = t * 4;
    float in[4] = {v.x, v.y, v.z, v.w};
    float4 r;
    float* rr = (float*)&r;
#pragma unroll
    for (int j = 0; j < 4; j++) {
        float y = (in[j] - mean) * rstd * gw[c + j] + gb[c + j];
        rr[j] = 0.5f * y * (1.f + erff(y * 0.70710678118654752f));
    }
    p[t] = r;
}

// ------------------------- v' = v + depthwise3x3(v)  -> vout[b][d][pos][e] -------------------------
__global__ void vlocal_kernel(const float* __restrict__ kv, const float* __restrict__ lw,
                              const float* __restrict__ lb, float* __restrict__ vout,
                              int n, int h, int w, int total) {
    int idx = blockIdx.x * 256 + threadIdx.x;
    if (idx >= total) return;
    int e   = idx & 63;
    int pos = (idx >> 6) % n;
    int d   = (idx / (64 * n)) & 3;
    int b   = idx / (64 * n * 4);
    int y = pos / w, xx = pos - y * w;
    int a = e >> 5, c = e & 31;
    int ch = a * 128 + c * 4 + d;
    float sum = lb[ch];
#pragma unroll
    for (int kh = 0; kh < 3; kh++) {
        int iy = y + kh - 1;
        if (iy < 0 || iy >= h) continue;
#pragma unroll
        for (int kw = 0; kw < 3; kw++) {
            int ix = xx + kw - 1;
            if (ix < 0 || ix >= w) continue;
            sum += lw[ch * 9 + kh * 3 + kw] *
                   kv[((size_t)b * n + iy * w + ix) * CDIM + 256 + d * 64 + e];
        }
    }
    float v0 = kv[((size_t)b * n + pos) * CDIM + 256 + d * 64 + e];
    vout[idx] = v0 + sum;
}

// ------------------------- flash-style attention (48KB static smem, no attribute call) -------------------------
// grid: (NTOK/64, 8 heads, B). Bq=Bk=64. 256 threads as 16x16, 4x4 per thread.
// Q/K stored transposed [e][r] with XOR swizzle. Ps ALIASES Kt (Kt dead after S-compute).
__global__ void __launch_bounds__(256) attn_kernel(
    const float* __restrict__ q,
    const float* __restrict__ kvA, const float* __restrict__ vA,
    const float* __restrict__ kvB, const float* __restrict__ vB,
    float* __restrict__ out) {
    __shared__ float Qt[4096];      // 16KB, [e][r] swizzled
    __shared__ float KP[4096];      // 16KB, Kt during S-compute, then Ps
    __shared__ float Vs[4096];      // 16KB, [kpos][e]
    const int qt = blockIdx.x, hg = blockIdx.y, b = blockIdx.z;
    const int br = hg >> 2, d = hg & 3;
    const int n = br ? N2 : N1;
    const float* kv = br ? kvB : kvA;
    const float* vv = br ? vB : vA;
    const int tid = threadIdx.x;
    const int tx = tid & 15, ty = tid >> 4;
    const float scale = 0.125f;   // 64^-0.5

    // load Q tile, transposed + prescaled
#pragma unroll
    for (int it = 0; it < 4; it++) {
        int f = tid + it * 256;
        int r = f >> 4;
        int e0 = (f & 15) * 4;
        float4 v = *(const float4*)(q + ((size_t)(b * NTOK + qt * 64 + r)) * CDIM + hg * 64 + e0);
        float vs[4] = {v.x * scale, v.y * scale, v.z * scale, v.w * scale};
#pragma unroll
        for (int j = 0; j < 4; j++) {
            int e = e0 + j;
            int slot = (r >> 2) ^ ((e >> 2) & 15);
            Qt[e * 64 + slot * 4 + (r & 3)] = vs[j];
        }
    }

    float m[4], l[4], o[4][4];
#pragma unroll
    for (int i = 0; i < 4; i++) {
        m[i] = -1e30f; l[i] = 0.f;
#pragma unroll
        for (int j = 0; j < 4; j++) o[i][j] = 0.f;
    }

    for (int k0 = 0; k0 < n; k0 += 64) {
        __syncthreads();   // prev-iter P*V reads of KP/Vs done (also covers Qt initial fill)
#pragma unroll
        for (int it = 0; it < 4; it++) {
            int f = tid + it * 256;
            int r = f >> 4;
            int e0 = (f & 15) * 4;
            float4 kvv = *(const float4*)(kv + ((size_t)b * n + k0 + r) * CDIM + d * 64 + e0);
            float kr[4] = {kvv.x, kvv.y, kvv.z, kvv.w};
#pragma unroll
            for (int j = 0; j < 4; j++) {
                int e = e0 + j;
                int slot = (r >> 2) ^ ((e >> 2) & 15);
                KP[e * 64 + slot * 4 + (r & 3)] = kr[j];
            }
            float4 vvv = *(const float4*)(vv + ((size_t)(b * 4 + d) * n + k0 + r) * 64 + e0);
            *(float4*)&Vs[r * 64 + e0] = vvv;
        }
        __syncthreads();

        // S = (Q*scale) K^T
        float s[4][4];
#pragma unroll
        for (int i = 0; i < 4; i++)
#pragma unroll
            for (int j = 0; j < 4; j++) s[i][j] = 0.f;
#pragma unroll 4
        for (int e = 0; e < 64; e++) {
            int sw = (e >> 2) & 15;
            float4 a4 = *(const float4*)&Qt[e * 64 + (ty ^ sw) * 4];
            float4 b4 = *(const float4*)&KP[e * 64 + (tx ^ sw) * 4];
            float ar[4] = {a4.x, a4.y, a4.z, a4.w};
            float brr[4] = {b4.x, b4.y, b4.z, b4.w};
#pragma unroll
            for (int i = 0; i < 4; i++)
#pragma unroll
                for (int j = 0; j < 4; j++) s[i][j] += ar[i] * brr[j];
        }
        __syncthreads();   // all K reads done before KP is overwritten with P

        // online softmax update + write P into KP
#pragma unroll
        for (int i = 0; i < 4; i++) {
            float mx = fmaxf(fmaxf(s[i][0], s[i][1]), fmaxf(s[i][2], s[i][3]));
#pragma unroll
            for (int off = 8; off; off >>= 1)
                mx = fmaxf(mx, __shfl_xor_sync(0xffffffffu, mx, off, 16));
            float mnew = fmaxf(m[i], mx);
            float fac = __expf(m[i] - mnew);
            m[i] = mnew;
            float rsum = 0.f;
#pragma unroll
            for (int j = 0; j < 4; j++) {
                float p = __expf(s[i][j] - mnew);
                s[i][j] = p;
                rsum += p;
            }
#pragma unroll
            for (int off = 8; off; off >>= 1)
                rsum += __shfl_xor_sync(0xffffffffu, rsum, off, 16);
            l[i] = l[i] * fac + rsum;
#pragma unroll
            for (int j = 0; j < 4; j++) o[i][j] *= fac;
            float4 pv = make_float4(s[i][0], s[i][1], s[i][2], s[i][3]);
            *(float4*)&KP[(ty * 4 + i) * 64 + tx * 4] = pv;
        }
        __syncthreads();

        // O += P V (P in KP, row-major [r][kpos])
#pragma unroll 4
        for (int k = 0; k < 64; k += 4) {
            float4 a0 = *(const float4*)&KP[(ty * 4 + 0) * 64 + k];
            float4 a1 = *(const float4*)&KP[(ty * 4 + 1) * 64 + k];
            float4 a2 = *(const float4*)&KP[(ty * 4 + 2) * 64 + k];
            float4 a3 = *(const float4*)&KP[(ty * 4 + 3) * 64 + k];
            float ar[4][4] = {{a0.x, a0.y, a0.z, a0.w}, {a1.x, a1.y, a1.z, a1.w},
                              {a2.x, a2.y, a2.z, a2.w}, {a3.x, a3.y, a3.z, a3.w}};
#pragma unroll
            for (int kk = 0; kk < 4; kk++) {
                float4 b4 = *(const float4*)&Vs[(k + kk) * 64 + tx * 4];
                float brr[4] = {b4.x, b4.y, b4.z, b4.w};
#pragma unroll
                for (int i = 0; i < 4; i++)
#pragma unroll
                    for (int j = 0; j < 4; j++) o[i][j] += ar[i][kk] * brr[j];
            }
        }
    }

#pragma unroll
    for (int i = 0; i < 4; i++) {
        float inv = 1.f / l[i];
        float4 r4 = make_float4(o[i][0] * inv, o[i][1] * inv, o[i][2] * inv, o[i][3] * inv);
        *(float4*)(out + ((size_t)(b * NTOK + qt * 64 + ty * 4 + i)) * CDIM + hg * 64 + tx * 4) = r4;
    }
}

// ------------------------- orchestration -------------------------
extern "C" void kernel_launch(void* const* d_in, const int* in_sizes, int n_in,
                              void* d_out, int out_size) {
    const float* x      = (const float*)d_in[0];
    const float* q_w    = (const float*)d_in[3];
    const float* sr1_w  = (const float*)d_in[4];
    const float* sr1_b  = (const float*)d_in[5];
    const float* n1w    = (const float*)d_in[6];
    const float* n1b    = (const float*)d_in[7];
    const float* sr2_w  = (const float*)d_in[8];
    const float* sr2_b  = (const float*)d_in[9];
    const float* n2w    = (const float*)d_in[10];
    const float* n2b    = (const float*)d_in[11];
    const float* kv1_w  = (const float*)d_in[12];
    const float* kv2_w  = (const float*)d_in[13];
    const float* lc1_w  = (const float*)d_in[14];
    const float* lc1_b  = (const float*)d_in[15];
    const float* lc2_w  = (const float*)d_in[16];
    const float* lc2_b  = (const float*)d_in[17];
    const float* proj_w = (const float*)d_in[18];
    const float* proj_b = (const float*)d_in[19];
    float* out = (float*)d_out;

    float *p_q, *p_wt1, *p_wt2, *p_x1, *p_x2,
          *p_kv1, *p_kv2, *p_v1, *p_v2, *p_att;
    cudaGetSymbolAddress((void**)&p_q,    g_q);
    cudaGetSymbolAddress((void**)&p_wt1,  g_wt1);
    cudaGetSymbolAddress((void**)&p_wt2,  g_wt2);
    cudaGetSymbolAddress((void**)&p_x1,   g_x1);
    cudaGetSymbolAddress((void**)&p_x2,   g_x2);
    cudaGetSymbolAddress((void**)&p_kv1,  g_kv1);
    cudaGetSymbolAddress((void**)&p_kv2,  g_kv2);
    cudaGetSymbolAddress((void**)&p_v1,   g_v1);
    cudaGetSymbolAddress((void**)&p_v2,   g_v2);
    cudaGetSymbolAddress((void**)&p_att,  g_att);

    // weight transposes (OIHW -> [co][khw][ci])
    wtrans_kernel<<<(CDIM * K1 + 255) / 256, 256>>>(sr1_w, p_wt1, KHW1);
    wtrans_kernel<<<(CDIM * K2 + 255) / 256, 256>>>(sr2_w, p_wt2, KHW2);

    // implicit-GEMM convs (+bias), output token-major [B*n, C]
    dim3 g1(CDIM / 128, BATCH * N1 / 128);
    dim3 g2(CDIM / 128, BATCH * N2 / 128);
    convgemm_kernel<4, 5, 4><<<g1, 256>>>(x, p_wt1, sr1_b, p_x1, K1);
    convgemm_kernel<5, 3, 2><<<g2, 256>>>(x, p_wt2, sr2_b, p_x2, K2);

    // LN + GELU (in place)
    ln_gelu_kernel<<<BATCH * N1, 128>>>(p_x1, n1w, n1b);
    ln_gelu_kernel<<<BATCH * N2, 128>>>(p_x2, n2w, n2b);

    // q / kv projections
    dim3 gq(CDIM / 128, BATCH * NTOK / 128);
    sgemm_kernel<false><<<gq, 256>>>(x, q_w, nullptr, p_q, BATCH * NTOK, CDIM, CDIM);
    sgemm_kernel<false><<<g1, 256>>>(p_x1, kv1_w, nullptr, p_kv1, BATCH * N1, CDIM, CDIM);
    sgemm_kernel<false><<<g2, 256>>>(p_x2, kv2_w, nullptr, p_kv2, BATCH * N2, CDIM, CDIM);

    // v' = v + depthwise local conv
    vlocal_kernel<<<(BATCH * HH * N1 * HDIM) / 256, 256>>>(p_kv1, lc1_w, lc1_b, p_v1, N1, H1, W1,
                                                           BATCH * HH * N1 * HDIM);
    vlocal_kernel<<<(BATCH * HH * N2 * HDIM) / 256, 256>>>(p_kv2, lc2_w, lc2_b, p_v2, N2, H2, W2,
                                                           BATCH * HH * N2 * HDIM);

    // attention (both branches in one launch; heads 0-3 -> branch1, 4-7 -> branch2)
    attn_kernel<<<dim3(NTOK / 64, 8, BATCH), 256>>>(p_q, p_kv1, p_v1, p_kv2, p_v2, p_att);

    // output projection (+bias)
    sgemm_kernel<true><<<gq, 256>>>(p_att, proj_w, proj_b, out, BATCH * NTOK, CDIM, CDIM);
}

// round 7
// speedup vs baseline: 1.6782x; 1.6782x over previous
#include <cuda_runtime.h>
#include <math.h>
#include <stdint.h>

// ------------------------- problem sizes -------------------------
#define BATCH 8
#define NTOK  4096
#define CDIM  512
#define HDIM  64
#define HH    4
#define H0    64
#define W0    64
#define N1 256
#define H1 16
#define W1 16
#define KHW1 25
#define K1 (KHW1*CDIM)   // 12800
#define N2 1024
#define H2 32
#define W2 32
#define KHW2 9
#define K2 (KHW2*CDIM)   // 4608

// ------------------------- scratch (device globals; no allocation) -------------------------
__device__ float g_q    [BATCH*NTOK*CDIM];
__device__ float g_wt1  [CDIM*K1];
__device__ float g_wt2  [CDIM*K2];
__device__ float g_wtq  [CDIM*CDIM];
__device__ float g_wtkv1[CDIM*CDIM];
__device__ float g_wtkv2[CDIM*CDIM];
__device__ float g_wtpr [CDIM*CDIM];
__device__ float g_x1   [BATCH*N1*CDIM];
__device__ float g_x2   [BATCH*N2*CDIM];
__device__ float g_kv1  [BATCH*N1*CDIM];
__device__ float g_kv2  [BATCH*N2*CDIM];
__device__ float g_v1   [BATCH*HH*N1*HDIM];
__device__ float g_v2   [BATCH*HH*N2*HDIM];
__device__ float g_att  [BATCH*NTOK*CDIM];

// ------------------------- mma.sync tf32 helpers -------------------------
__device__ __forceinline__ uint32_t f2tf32(float f) {
    uint32_t u;
    asm("cvt.rna.tf32.f32 %0, %1;" : "=r"(u) : "f"(f));
    return u;
}
__device__ __forceinline__ void mma16n8k8(float* c, const uint32_t* a, const uint32_t* b) {
    asm volatile(
        "mma.sync.aligned.m16n8k8.row.col.f32.tf32.tf32.f32 "
        "{%0,%1,%2,%3}, {%4,%5,%6,%7}, {%8,%9}, {%0,%1,%2,%3};"
        : "+f"(c[0]), "+f"(c[1]), "+f"(c[2]), "+f"(c[3])
        : "r"(a[0]), "r"(a[1]), "r"(a[2]), "r"(a[3]), "r"(b[0]), "r"(b[1]));
}

// smem row stride in words (16 data + 4 pad; 80B rows keep float4 alignment,
// and stride 20 mod 32 gives 8 distinct banks across the 8 fragment rows)
#define RS 20

// ------------------------- tf32 mma.sync GEMM (128x128 tile, KT=16, 2-stage) ------------
// MODE 0: dense A[M,K]. MODE 1: implicit-im2col A from x[B,4096,512] (k = s*512+ci).
// B: Wt[N total rows][K] K-major. Grid (N/128, M/128). 256 threads (8 warps, 2x4).
template<int MODE, int OWS, int KW, int STRIDE, bool BIAS>
__global__ void __launch_bounds__(256) mma_gemm_kernel(
    const float* __restrict__ A, const float* __restrict__ Bw,
    const float* __restrict__ bias, float* __restrict__ C, int K) {
    __shared__ uint32_t As[2][128 * RS];
    __shared__ uint32_t Bs[2][128 * RS];
    const int tid = threadIdx.x;
    const int wid = tid >> 5, lane = tid & 31;
    const int gid = lane >> 2, tig = lane & 3;
    const int warp_m = wid >> 2;          // 0..1 -> 64 rows each
    const int warp_n = wid & 3;           // 0..3 -> 32 cols each
    const int blkn = blockIdx.x, blkm = blockIdx.y;

    float acc[4][4][4];
#pragma unroll
    for (int i = 0; i < 4; i++)
#pragma unroll
        for (int j = 0; j < 4; j++)
#pragma unroll
            for (int f = 0; f < 4; f++) acc[i][j][f] = 0.f;

    const int nc = K >> 4;

    // ---- stage fill helper (as lambda via macro-ish inline code) ----
    auto fill = [&](int s, int c) {
        const int k0 = c << 4;
        // A tile: 128 rows x 16 floats
        if (MODE == 0) {
#pragma unroll
            for (int i = 0; i < 2; i++) {
                int f4 = tid + i * 256;
                int row = f4 >> 2, c4 = f4 & 3;
                float4 v = *(const float4*)(A + (size_t)(blkm * 128 + row) * K + k0 + c4 * 4);
                uint32_t* d = &As[s][row * RS + c4 * 4];
                d[0] = f2tf32(v.x); d[1] = f2tf32(v.y); d[2] = f2tf32(v.z); d[3] = f2tf32(v.w);
            }
        } else {
            const int sidx = k0 >> 9;
            const int ci0 = k0 & 511;
            const int kh = sidx / KW, kw = sidx - kh * KW;
#pragma unroll
            for (int i = 0; i < 2; i++) {
                int f4 = tid + i * 256;
                int row = f4 >> 2, c4 = f4 & 3;
                int m = blkm * 128 + row;
                int b = m >> (2 * OWS);
                int pos = m & ((1 << (2 * OWS)) - 1);
                int oh = pos >> OWS, ow = pos & ((1 << OWS) - 1);
                int ih = oh * STRIDE - 1 + kh;
                int iw = ow * STRIDE - 1 + kw;
                float4 v = make_float4(0.f, 0.f, 0.f, 0.f);
                if (ih >= 0 && ih < H0 && iw >= 0 && iw < W0)
                    v = *(const float4*)(A + ((size_t)b * NTOK + ih * W0 + iw) * CDIM + ci0 + c4 * 4);
                uint32_t* d = &As[s][row * RS + c4 * 4];
                d[0] = f2tf32(v.x); d[1] = f2tf32(v.y); d[2] = f2tf32(v.z); d[3] = f2tf32(v.w);
            }
        }
        // B tile: 128 rows x 16 floats
#pragma unroll
        for (int i = 0; i < 2; i++) {
            int f4 = tid + i * 256;
            int row = f4 >> 2, c4 = f4 & 3;
            float4 v = *(const float4*)(Bw + (size_t)(blkn * 128 + row) * K + k0 + c4 * 4);
            uint32_t* d = &Bs[s][row * RS + c4 * 4];
            d[0] = f2tf32(v.x); d[1] = f2tf32(v.y); d[2] = f2tf32(v.z); d[3] = f2tf32(v.w);
        }
    };

    fill(0, 0);
    __syncthreads();

    for (int c = 0; c < nc; c++) {
        const int s = c & 1;
        if (c + 1 < nc) fill(s ^ 1, c + 1);
        // compute on stage s
#pragma unroll
        for (int kk = 0; kk < 2; kk++) {
            const int kb = kk * 8;
            uint32_t afr[4][4];
#pragma unroll
            for (int mi = 0; mi < 4; mi++) {
                int rb = (warp_m * 64 + mi * 16 + gid) * RS + kb;
                afr[mi][0] = As[s][rb + tig];
                afr[mi][1] = As[s][rb + 8 * RS + tig];
                afr[mi][2] = As[s][rb + tig + 4];
                afr[mi][3] = As[s][rb + 8 * RS + tig + 4];
            }
            uint32_t bfr[4][2];
#pragma unroll
            for (int ni = 0; ni < 4; ni++) {
                int nb = (warp_n * 32 + ni * 8 + gid) * RS + kb;
                bfr[ni][0] = Bs[s][nb + tig];
                bfr[ni][1] = Bs[s][nb + tig + 4];
            }
#pragma unroll
            for (int mi = 0; mi < 4; mi++)
#pragma unroll
                for (int ni = 0; ni < 4; ni++)
                    mma16n8k8(acc[mi][ni], afr[mi], bfr[ni]);
        }
        __syncthreads();
    }

    // ---- epilogue: registers -> gmem ----
#pragma unroll
    for (int mi = 0; mi < 4; mi++) {
        int row0 = blkm * 128 + warp_m * 64 + mi * 16 + gid;
#pragma unroll
        for (int ni = 0; ni < 4; ni++) {
            int col = blkn * 128 + warp_n * 32 + ni * 8 + tig * 2;
            float b0 = 0.f, b1 = 0.f;
            if (BIAS) { b0 = bias[col]; b1 = bias[col + 1]; }
            float2 v0 = make_float2(acc[mi][ni][0] + b0, acc[mi][ni][1] + b1);
            float2 v1 = make_float2(acc[mi][ni][2] + b0, acc[mi][ni][3] + b1);
            *(float2*)(C + (size_t)row0 * CDIM + col) = v0;
            *(float2*)(C + (size_t)(row0 + 8) * CDIM + col) = v1;
        }
    }
}

// ------------------------- weight transposes -------------------------
__global__ void wtrans_kernel(const float* __restrict__ w, float* __restrict__ wt, int KHW) {
    int idx = blockIdx.x * 256 + threadIdx.x;
    int total = CDIM * KHW * CDIM;
    if (idx >= total) return;
    int ci = idx % CDIM;
    int s  = (idx / CDIM) % KHW;
    int co = idx / (CDIM * KHW);
    wt[idx] = w[(co * CDIM + ci) * KHW + s];
}
__global__ void ltrans_kernel(const float* __restrict__ w, float* __restrict__ wt) {
    int idx = blockIdx.x * 256 + threadIdx.x;
    int n = idx >> 9, k = idx & 511;
    wt[idx] = w[k * CDIM + n];
}

// ------------------------- LayerNorm + exact GELU -------------------------
__global__ void ln_gelu_kernel(float* __restrict__ x, const float* __restrict__ gw,
                               const float* __restrict__ gb) {
    __shared__ float rs_[4], rs2_[4];
    int row = blockIdx.x;
    int t = threadIdx.x;
    float4* p = (float4*)(x + (size_t)row * CDIM);
    float4 v = p[t];
    float s  = v.x + v.y + v.z + v.w;
    float s2 = v.x * v.x + v.y * v.y + v.z * v.z + v.w * v.w;
#pragma unroll
    for (int o = 16; o; o >>= 1) {
        s  += __shfl_xor_sync(0xffffffffu, s, o);
        s2 += __shfl_xor_sync(0xffffffffu, s2, o);
    }
    int wid = t >> 5;
    if ((t & 31) == 0) { rs_[wid] = s; rs2_[wid] = s2; }
    __syncthreads();
    s  = rs_[0] + rs_[1] + rs_[2] + rs_[3];
    s2 = rs2_[0] + rs2_[1] + rs2_[2] + rs2_[3];
    float mean = s * (1.f / 512.f);
    float var  = s2 * (1.f / 512.f) - mean * mean;
    float rstd = rsqrtf(var + 1e-5f);
    int c = t * 4;
    float in[4] = {v.x, v.y, v.z, v.w};
    float4 r;
    float* rr = (float*)&r;
#pragma unroll
    for (int j = 0; j < 4; j++) {
        float y = (in[j] - mean) * rstd * gw[c + j] + gb[c + j];
        rr[j] = 0.5f * y * (1.f + erff(y * 0.70710678118654752f));
    }
    p[t] = r;
}

// ------------------------- v' = v + depthwise3x3(v) -------------------------
__global__ void vlocal_kernel(const float* __restrict__ kv, const float* __restrict__ lw,
                              const float* __restrict__ lb, float* __restrict__ vout,
                              int n, int h, int w, int total) {
    int idx = blockIdx.x * 256 + threadIdx.x;
    if (idx >= total) return;
    int e   = idx & 63;
    int pos = (idx >> 6) % n;
    int d   = (idx / (64 * n)) & 3;
    int b   = idx / (64 * n * 4);
    int y = pos / w, xx = pos - y * w;
    int a = e >> 5, c = e & 31;
    int ch = a * 128 + c * 4 + d;
    float sum = lb[ch];
#pragma unroll
    for (int kh = 0; kh < 3; kh++) {
        int iy = y + kh - 1;
        if (iy < 0 || iy >= h) continue;
#pragma unroll
        for (int kw = 0; kw < 3; kw++) {
            int ix = xx + kw - 1;
            if (ix < 0 || ix >= w) continue;
            sum += lw[ch * 9 + kh * 3 + kw] *
                   kv[((size_t)b * n + iy * w + ix) * CDIM + 256 + d * 64 + e];
        }
    }
    float v0 = kv[((size_t)b * n + pos) * CDIM + 256 + d * 64 + e];
    vout[idx] = v0 + sum;
}

// ------------------------- flash-style attention (48KB static smem) -------------------------
__global__ void __launch_bounds__(256) attn_kernel(
    const float* __restrict__ q,
    const float* __restrict__ kvA, const float* __restrict__ vA,
    const float* __restrict__ kvB, const float* __restrict__ vB,
    float* __restrict__ out) {
    __shared__ float Qt[4096];
    __shared__ float KP[4096];
    __shared__ float Vs[4096];
    const int qt = blockIdx.x, hg = blockIdx.y, b = blockIdx.z;
    const int br = hg >> 2, d = hg & 3;
    const int n = br ? N2 : N1;
    const float* kv = br ? kvB : kvA;
    const float* vv = br ? vB : vA;
    const int tid = threadIdx.x;
    const int tx = tid & 15, ty = tid >> 4;
    const float scale = 0.125f;

#pragma unroll
    for (int it = 0; it < 4; it++) {
        int f = tid + it * 256;
        int r = f >> 4;
        int e0 = (f & 15) * 4;
        float4 v = *(const float4*)(q + ((size_t)(b * NTOK + qt * 64 + r)) * CDIM + hg * 64 + e0);
        float vs[4] = {v.x * scale, v.y * scale, v.z * scale, v.w * scale};
#pragma unroll
        for (int j = 0; j < 4; j++) {
            int e = e0 + j;
            int slot = (r >> 2) ^ ((e >> 2) & 15);
            Qt[e * 64 + slot * 4 + (r & 3)] = vs[j];
        }
    }

    float m[4], l[4], o[4][4];
#pragma unroll
    for (int i = 0; i < 4; i++) {
        m[i] = -1e30f; l[i] = 0.f;
#pragma unroll
        for (int j = 0; j < 4; j++) o[i][j] = 0.f;
    }

    for (int k0 = 0; k0 < n; k0 += 64) {
        __syncthreads();
#pragma unroll
        for (int it = 0; it < 4; it++) {
            int f = tid + it * 256;
            int r = f >> 4;
            int e0 = (f & 15) * 4;
            float4 kvv = *(const float4*)(kv + ((size_t)b * n + k0 + r) * CDIM + d * 64 + e0);
            float kr[4] = {kvv.x, kvv.y, kvv.z, kvv.w};
#pragma unroll
            for (int j = 0; j < 4; j++) {
                int e = e0 + j;
                int slot = (r >> 2) ^ ((e >> 2) & 15);
                KP[e * 64 + slot * 4 + (r & 3)] = kr[j];
            }
            float4 vvv = *(const float4*)(vv + ((size_t)(b * 4 + d) * n + k0 + r) * 64 + e0);
            *(float4*)&Vs[r * 64 + e0] = vvv;
        }
        __syncthreads();

        float s[4][4];
#pragma unroll
        for (int i = 0; i < 4; i++)
#pragma unroll
            for (int j = 0; j < 4; j++) s[i][j] = 0.f;
#pragma unroll 4
        for (int e = 0; e < 64; e++) {
            int sw = (e >> 2) & 15;
            float4 a4 = *(const float4*)&Qt[e * 64 + (ty ^ sw) * 4];
            float4 b4 = *(const float4*)&KP[e * 64 + (tx ^ sw) * 4];
            float ar[4] = {a4.x, a4.y, a4.z, a4.w};
            float brr[4] = {b4.x, b4.y, b4.z, b4.w};
#pragma unroll
            for (int i = 0; i < 4; i++)
#pragma unroll
                for (int j = 0; j < 4; j++) s[i][j] += ar[i] * brr[j];
        }
        __syncthreads();

#pragma unroll
        for (int i = 0; i < 4; i++) {
            float mx = fmaxf(fmaxf(s[i][0], s[i][1]), fmaxf(s[i][2], s[i][3]));
#pragma unroll
            for (int off = 8; off; off >>= 1)
                mx = fmaxf(mx, __shfl_xor_sync(0xffffffffu, mx, off, 16));
            float mnew = fmaxf(m[i], mx);
            float fac = __expf(m[i] - mnew);
            m[i] = mnew;
            float rsum = 0.f;
#pragma unroll
            for (int j = 0; j < 4; j++) {
                float p = __expf(s[i][j] - mnew);
                s[i][j] = p;
                rsum += p;
            }
#pragma unroll
            for (int off = 8; off; off >>= 1)
                rsum += __shfl_xor_sync(0xffffffffu, rsum, off, 16);
            l[i] = l[i] * fac + rsum;
#pragma unroll
            for (int j = 0; j < 4; j++) o[i][j] *= fac;
            float4 pv = make_float4(s[i][0], s[i][1], s[i][2], s[i][3]);
            *(float4*)&KP[(ty * 4 + i) * 64 + tx * 4] = pv;
        }
        __syncthreads();

#pragma unroll 4
        for (int k = 0; k < 64; k += 4) {
            float4 a0 = *(const float4*)&KP[(ty * 4 + 0) * 64 + k];
            float4 a1 = *(const float4*)&KP[(ty * 4 + 1) * 64 + k];
            float4 a2 = *(const float4*)&KP[(ty * 4 + 2) * 64 + k];
            float4 a3 = *(const float4*)&KP[(ty * 4 + 3) * 64 + k];
            float ar[4][4] = {{a0.x, a0.y, a0.z, a0.w}, {a1.x, a1.y, a1.z, a1.w},
                              {a2.x, a2.y, a2.z, a2.w}, {a3.x, a3.y, a3.z, a3.w}};
#pragma unroll
            for (int kk = 0; kk < 4; kk++) {
                float4 b4 = *(const float4*)&Vs[(k + kk) * 64 + tx * 4];
                float brr[4] = {b4.x, b4.y, b4.z, b4.w};
#pragma unroll
                for (int i = 0; i < 4; i++)
#pragma unroll
                    for (int j = 0; j < 4; j++) o[i][j] += ar[i][kk] * brr[j];
            }
        }
    }

#pragma unroll
    for (int i = 0; i < 4; i++) {
        float inv = 1.f / l[i];
        float4 r4 = make_float4(o[i][0] * inv, o[i][1] * inv, o[i][2] * inv, o[i][3] * inv);
        *(float4*)(out + ((size_t)(b * NTOK + qt * 64 + ty * 4 + i)) * CDIM + hg * 64 + tx * 4) = r4;
    }
}

// ------------------------- orchestration -------------------------
extern "C" void kernel_launch(void* const* d_in, const int* in_sizes, int n_in,
                              void* d_out, int out_size) {
    const float* x      = (const float*)d_in[0];
    const float* q_w    = (const float*)d_in[3];
    const float* sr1_w  = (const float*)d_in[4];
    const float* sr1_b  = (const float*)d_in[5];
    const float* n1w    = (const float*)d_in[6];
    const float* n1b    = (const float*)d_in[7];
    const float* sr2_w  = (const float*)d_in[8];
    const float* sr2_b  = (const float*)d_in[9];
    const float* n2w    = (const float*)d_in[10];
    const float* n2b    = (const float*)d_in[11];
    const float* kv1_w  = (const float*)d_in[12];
    const float* kv2_w  = (const float*)d_in[13];
    const float* lc1_w  = (const float*)d_in[14];
    const float* lc1_b  = (const float*)d_in[15];
    const float* lc2_w  = (const float*)d_in[16];
    const float* lc2_b  = (const float*)d_in[17];
    const float* proj_w = (const float*)d_in[18];
    const float* proj_b = (const float*)d_in[19];
    float* out = (float*)d_out;

    float *p_q, *p_wt1, *p_wt2, *p_wtq, *p_wtkv1, *p_wtkv2, *p_wtpr,
          *p_x1, *p_x2, *p_kv1, *p_kv2, *p_v1, *p_v2, *p_att;
    cudaGetSymbolAddress((void**)&p_q,     g_q);
    cudaGetSymbolAddress((void**)&p_wt1,   g_wt1);
    cudaGetSymbolAddress((void**)&p_wt2,   g_wt2);
    cudaGetSymbolAddress((void**)&p_wtq,   g_wtq);
    cudaGetSymbolAddress((void**)&p_wtkv1, g_wtkv1);
    cudaGetSymbolAddress((void**)&p_wtkv2, g_wtkv2);
    cudaGetSymbolAddress((void**)&p_wtpr,  g_wtpr);
    cudaGetSymbolAddress((void**)&p_x1,    g_x1);
    cudaGetSymbolAddress((void**)&p_x2,    g_x2);
    cudaGetSymbolAddress((void**)&p_kv1,   g_kv1);
    cudaGetSymbolAddress((void**)&p_kv2,   g_kv2);
    cudaGetSymbolAddress((void**)&p_v1,    g_v1);
    cudaGetSymbolAddress((void**)&p_v2,    g_v2);
    cudaGetSymbolAddress((void**)&p_att,   g_att);

    // weight transposes
    wtrans_kernel<<<(CDIM * K1 + 255) / 256, 256>>>(sr1_w, p_wt1, KHW1);
    wtrans_kernel<<<(CDIM * K2 + 255) / 256, 256>>>(sr2_w, p_wt2, KHW2);
    ltrans_kernel<<<(CDIM * CDIM) / 256, 256>>>(q_w, p_wtq);
    ltrans_kernel<<<(CDIM * CDIM) / 256, 256>>>(kv1_w, p_wtkv1);
    ltrans_kernel<<<(CDIM * CDIM) / 256, 256>>>(kv2_w, p_wtkv2);
    ltrans_kernel<<<(CDIM * CDIM) / 256, 256>>>(proj_w, p_wtpr);

    // implicit-GEMM convs (tf32 mma.sync, +bias)
    mma_gemm_kernel<1, 4, 5, 4, true><<<dim3(4, BATCH * N1 / 128), 256>>>(x, p_wt1, sr1_b, p_x1, K1);
    mma_gemm_kernel<1, 5, 3, 2, true><<<dim3(4, BATCH * N2 / 128), 256>>>(x, p_wt2, sr2_b, p_x2, K2);

    // LN + GELU
    ln_gelu_kernel<<<BATCH * N1, 128>>>(p_x1, n1w, n1b);
    ln_gelu_kernel<<<BATCH * N2, 128>>>(p_x2, n2w, n2b);

    // projections (tf32 mma.sync)
    mma_gemm_kernel<0, 0, 0, 0, false><<<dim3(4, BATCH * NTOK / 128), 256>>>(x, p_wtq, nullptr, p_q, CDIM);
    mma_gemm_kernel<0, 0, 0, 0, false><<<dim3(4, BATCH * N1 / 128), 256>>>(p_x1, p_wtkv1, nullptr, p_kv1, CDIM);
    mma_gemm_kernel<0, 0, 0, 0, false><<<dim3(4, BATCH * N2 / 128), 256>>>(p_x2, p_wtkv2, nullptr, p_kv2, CDIM);

    // v' = v + depthwise local conv
    vlocal_kernel<<<(BATCH * HH * N1 * HDIM) / 256, 256>>>(p_kv1, lc1_w, lc1_b, p_v1, N1, H1, W1,
                                                           BATCH * HH * N1 * HDIM);
    vlocal_kernel<<<(BATCH * HH * N2 * HDIM) / 256, 256>>>(p_kv2, lc2_w, lc2_b, p_v2, N2, H2, W2,
                                                           BATCH * HH * N2 * HDIM);

    // attention
    attn_kernel<<<dim3(NTOK / 64, 8, BATCH), 256>>>(p_q, p_kv1, p_v1, p_kv2, p_v2, p_att);

    // output projection (tf32 mma.sync, +bias)
    mma_gemm_kernel<0, 0, 0, 0, true><<<dim3(4, BATCH * NTOK / 128), 256>>>(p_att, p_wtpr, proj_b, out, CDIM);
}